// round 1
// baseline (speedup 1.0000x reference)
#include <cuda_runtime.h>

#define WARP_FULL 0xFFFFFFFFu

namespace {
constexpr int NMAX = 100000;
constexpr int EMAX = 3200000;
constexpr int HD = 32;
constexpr int NLAYER = 3;
constexpr int SCAN_CHUNK = 4096;   // 1024 threads * 4 items
constexpr int MAXCHUNK = 64;
}

// ---- persistent device scratch (no runtime allocations allowed) ----
__device__ __align__(128) float g_A[(size_t)NMAX * HD];
__device__ __align__(128) float g_h[(size_t)NMAX * HD];
__device__ __align__(16)  float g_V[(size_t)NMAX * 2];
__device__ __align__(16)  float g_Cfeat[(size_t)NMAX * 4];
__device__ float g_Ccnt[NMAX];
__device__ int   g_deg[NMAX];
__device__ int   g_rowptr[NMAX + 1];
__device__ int   g_cursor[NMAX];
__device__ int   g_srt_send[EMAX];
__device__ float g_srt_mask[EMAX];
__device__ int   g_srt_eid[EMAX];
__device__ float g_pooled[NLAYER * HD];
__device__ float g_gstate[HD];
__device__ int   g_chunksum[MAXCHUNK];
__device__ int   g_chunkoff[MAXCHUNK];

// ---------------------------------------------------------------- init/zero
__global__ void k_zero(int n) {
    int i = blockIdx.x * blockDim.x + threadIdx.x;
    int stride = gridDim.x * blockDim.x;
    for (int idx = i; idx < n; idx += stride) g_deg[idx] = 0;
    if (i < NLAYER * HD) g_pooled[i] = 0.f;
    if (i < HD) g_gstate[i] = 0.f;
}

// ---------------------------------------------------------------- histogram of receivers
__global__ void k_hist(const int* __restrict__ recv, int e) {
    int stride = gridDim.x * blockDim.x;
    for (int i = blockIdx.x * blockDim.x + threadIdx.x; i < e; i += stride)
        atomicAdd(&g_deg[recv[i]], 1);
}

// ---------------------------------------------------------------- 3-pass exclusive scan
__global__ void k_chunksum(int n) {
    int b = blockIdx.x, t = threadIdx.x;
    int base = b * SCAN_CHUNK + t * 4;
    int s = 0;
#pragma unroll
    for (int i = 0; i < 4; i++) { int idx = base + i; if (idx < n) s += g_deg[idx]; }
    __shared__ int sr[1024];
    sr[t] = s; __syncthreads();
    for (int off = 512; off > 0; off >>= 1) {
        if (t < off) sr[t] += sr[t + off];
        __syncthreads();
    }
    if (t == 0) g_chunksum[b] = sr[0];
}

__global__ void k_chunkoff(int nch, int n, int e) {
    if (threadIdx.x == 0 && blockIdx.x == 0) {
        int acc = 0;
        for (int i = 0; i < nch; i++) { g_chunkoff[i] = acc; acc += g_chunksum[i]; }
        g_rowptr[n] = e;
    }
}

__global__ void k_scanfinal(int n) {
    int b = blockIdx.x, t = threadIdx.x;
    int base = b * SCAN_CHUNK + t * 4;
    int d0 = 0, d1 = 0, d2 = 0, d3 = 0;
    if (base + 0 < n) d0 = g_deg[base + 0];
    if (base + 1 < n) d1 = g_deg[base + 1];
    if (base + 2 < n) d2 = g_deg[base + 2];
    if (base + 3 < n) d3 = g_deg[base + 3];
    int tsum = d0 + d1 + d2 + d3;
    __shared__ int sc[1024];
    sc[t] = tsum; __syncthreads();
    for (int off = 1; off < 1024; off <<= 1) {
        int v = (t >= off) ? sc[t - off] : 0;
        __syncthreads();
        sc[t] += v;
        __syncthreads();
    }
    int excl = sc[t] - tsum + g_chunkoff[b];
    int p0 = excl, p1 = excl + d0, p2 = p1 + d1, p3 = p2 + d2;
    if (base + 0 < n) { g_rowptr[base + 0] = p0; g_cursor[base + 0] = p0; }
    if (base + 1 < n) { g_rowptr[base + 1] = p1; g_cursor[base + 1] = p1; }
    if (base + 2 < n) { g_rowptr[base + 2] = p2; g_cursor[base + 2] = p2; }
    if (base + 3 < n) { g_rowptr[base + 3] = p3; g_cursor[base + 3] = p3; }
}

// ---------------------------------------------------------------- edge scatter into CSR slots
__global__ void k_scatter(const int* __restrict__ send, const int* __restrict__ recv,
                          const float* __restrict__ mask, int e) {
    int stride = gridDim.x * blockDim.x;
    for (int i = blockIdx.x * blockDim.x + threadIdx.x; i < e; i += stride) {
        int r = recv[i];
        int pos = atomicAdd(&g_cursor[r], 1);
        g_srt_send[pos] = send[i];
        g_srt_mask[pos] = mask[i];
        g_srt_eid[pos]  = i;
    }
}

// ---------------------------------------------------------------- per-node edge-feature sums
__global__ __launch_bounds__(256) void k_cfeat(const float4* __restrict__ ef, int n) {
    int lane = threadIdx.x & 31;
    int wpb = blockDim.x >> 5;
    int gw = blockIdx.x * wpb + (threadIdx.x >> 5);
    int nw = gridDim.x * wpb;
    for (int v = gw; v < n; v += nw) {
        int beg = g_rowptr[v], end = g_rowptr[v + 1];
        float4 acc = make_float4(0.f, 0.f, 0.f, 0.f);
        float cnt = 0.f;
        for (int j = beg + lane; j < end; j += 32) {
            int eid = g_srt_eid[j];
            float mk = g_srt_mask[j];
            float4 f = ef[eid];
            acc.x += mk * f.x; acc.y += mk * f.y;
            acc.z += mk * f.z; acc.w += mk * f.w;
            cnt += mk;
        }
#pragma unroll
        for (int off = 16; off > 0; off >>= 1) {
            acc.x += __shfl_xor_sync(WARP_FULL, acc.x, off);
            acc.y += __shfl_xor_sync(WARP_FULL, acc.y, off);
            acc.z += __shfl_xor_sync(WARP_FULL, acc.z, off);
            acc.w += __shfl_xor_sync(WARP_FULL, acc.w, off);
            cnt   += __shfl_xor_sync(WARP_FULL, cnt, off);
        }
        if (lane == 0) {
            *(float4*)&g_Cfeat[(size_t)v * 4] = acc;
            g_Ccnt[v] = cnt;
        }
    }
}

// ---------------------------------------------------------------- A0 = [V0,h0] @ Wmsg0[:34], V init
__global__ __launch_bounds__(256) void k_initA(
    const float2* __restrict__ PQ, const float* __restrict__ Win,
    const float* __restrict__ bin, const float* __restrict__ Wmsg0, int n) {
    __shared__ float sWin[2][HD], sbin[HD], sWm[34][HD];
    int tid = threadIdx.x;
    for (int i = tid; i < 2 * HD; i += blockDim.x) sWin[i >> 5][i & 31] = Win[i];
    if (tid < HD) sbin[tid] = bin[tid];
    for (int i = tid; i < 34 * HD; i += blockDim.x) sWm[i >> 5][i & 31] = Wmsg0[i];
    __syncthreads();
    int lane = tid & 31, wpb = blockDim.x >> 5;
    int gw = blockIdx.x * wpb + (tid >> 5), nw = gridDim.x * wpb;
    for (int v = gw; v < n; v += nw) {
        float2 pq = PQ[v];
        float h0 = pq.x * sWin[0][lane] + pq.y * sWin[1][lane] + sbin[lane];
        float a = sWm[0][lane];  // V = (1, 0): row0 * 1 + row1 * 0
#pragma unroll
        for (int k = 0; k < HD; k++)
            a += __shfl_sync(WARP_FULL, h0, k) * sWm[2 + k][lane];
        g_A[(size_t)v * HD + lane] = a;
        if (lane == 0) *(float2*)&g_V[(size_t)v * 2] = make_float2(1.f, 0.f);
    }
}

// ---------------------------------------------------------------- hot SpMM: h = relu(S @ A + D)
__global__ __launch_bounds__(256) void k_agg(
    const float* __restrict__ W2,   // W_msg[l] rows 34..37 (4x32)
    const float* __restrict__ bm,   // b_msg[l]
    int layer, int n) {
    __shared__ float sW2[4][HD], sb[HD], spool[HD];
    int tid = threadIdx.x;
    if (tid < 4 * HD) sW2[tid >> 5][tid & 31] = W2[tid];
    if (tid < HD) { sb[tid] = bm[tid]; spool[tid] = 0.f; }
    __syncthreads();
    int lane = tid & 31, sub = lane >> 3, cg = lane & 7;
    int wpb = blockDim.x >> 5;
    int gw = blockIdx.x * wpb + (tid >> 5), nw = gridDim.x * wpb;
    float4 pacc = make_float4(0.f, 0.f, 0.f, 0.f);
    for (int v = gw; v < n; v += nw) {
        int beg = g_rowptr[v], end = g_rowptr[v + 1];
        float4 acc = make_float4(0.f, 0.f, 0.f, 0.f);
        // software pipeline: prefetch (sender, mask) for the next 4-edge batch
        int s = 0; float mk = 0.f;
        {
            int j0 = beg + sub;
            if (j0 < end) { s = g_srt_send[j0]; mk = g_srt_mask[j0]; }
        }
        for (int base = beg; base < end; base += 4) {
            int cs = s; float cmk = mk;
            int nj = base + 4 + sub;
            s = 0; mk = 0.f;
            if (nj < end) { s = g_srt_send[nj]; mk = g_srt_mask[nj]; }
            const float4 a = *(const float4*)(g_A + (size_t)cs * HD + (cg << 2));
            acc.x += cmk * a.x; acc.y += cmk * a.y;
            acc.z += cmk * a.z; acc.w += cmk * a.w;
        }
#pragma unroll
        for (int off = 8; off < 32; off <<= 1) {
            acc.x += __shfl_xor_sync(WARP_FULL, acc.x, off);
            acc.y += __shfl_xor_sync(WARP_FULL, acc.y, off);
            acc.z += __shfl_xor_sync(WARP_FULL, acc.z, off);
            acc.w += __shfl_xor_sync(WARP_FULL, acc.w, off);
        }
        if (sub == 0) {
            float4 cf = *(const float4*)&g_Cfeat[(size_t)v * 4];
            float cn = g_Ccnt[v];
            int c0 = cg << 2;
            float4 hv;
            hv.x = fmaxf(acc.x + cf.x * sW2[0][c0 + 0] + cf.y * sW2[1][c0 + 0] +
                         cf.z * sW2[2][c0 + 0] + cf.w * sW2[3][c0 + 0] + cn * sb[c0 + 0], 0.f);
            hv.y = fmaxf(acc.y + cf.x * sW2[0][c0 + 1] + cf.y * sW2[1][c0 + 1] +
                         cf.z * sW2[2][c0 + 1] + cf.w * sW2[3][c0 + 1] + cn * sb[c0 + 1], 0.f);
            hv.z = fmaxf(acc.z + cf.x * sW2[0][c0 + 2] + cf.y * sW2[1][c0 + 2] +
                         cf.z * sW2[2][c0 + 2] + cf.w * sW2[3][c0 + 2] + cn * sb[c0 + 2], 0.f);
            hv.w = fmaxf(acc.w + cf.x * sW2[0][c0 + 3] + cf.y * sW2[1][c0 + 3] +
                         cf.z * sW2[2][c0 + 3] + cf.w * sW2[3][c0 + 3] + cn * sb[c0 + 3], 0.f);
            *(float4*)(g_h + (size_t)v * HD + c0) = hv;
            pacc.x += hv.x; pacc.y += hv.y; pacc.z += hv.z; pacc.w += hv.w;
        }
    }
    if (sub == 0) {
        int c0 = cg << 2;
        atomicAdd(&spool[c0 + 0], pacc.x);
        atomicAdd(&spool[c0 + 1], pacc.y);
        atomicAdd(&spool[c0 + 2], pacc.z);
        atomicAdd(&spool[c0 + 3], pacc.w);
    }
    __syncthreads();
    if (tid < HD) atomicAdd(&g_pooled[layer * HD + tid], spool[tid]);
}

// ---------------------------------------------------------------- global supernode update (1 warp)
__global__ void k_g(const float* __restrict__ Wg, const float* __restrict__ bg,
                    int layer, float invn) {
    __shared__ float sg[HD], sp[HD];
    int c = threadIdx.x;  // 32 threads
    sg[c] = g_gstate[c];
    sp[c] = g_pooled[layer * HD + c] * invn;
    __syncwarp();
    float acc = bg[c];
#pragma unroll
    for (int k = 0; k < HD; k++) acc += sg[k] * Wg[k * HD + c];
#pragma unroll
    for (int k = 0; k < HD; k++) acc += sp[k] * Wg[(HD + k) * HD + c];
    g_gstate[c] = fmaxf(acc, 0.f);
}

// ---------------------------------------------------------------- node update + V residual + next A
template <bool LAST>
__global__ __launch_bounds__(256) void k_upd(
    const float* __restrict__ Wn,     // W_n[l] (64x32)
    const float* __restrict__ bn,     // b_n[l]
    const float* __restrict__ Wo,     // W_out[l] (32x2)
    const float* __restrict__ bo,     // b_out[l]
    const float* __restrict__ WmNext, // W_msg[l+1] rows 0..33 (unused if LAST)
    float* __restrict__ out, int n) {
    __shared__ float sWn[HD][HD], gterm[HD], sWm[34][HD], sWo0[HD], sWo1[HD], sg[HD];
    int tid = threadIdx.x;
    for (int i = tid; i < HD * HD; i += blockDim.x) sWn[i >> 5][i & 31] = Wn[i];
    if (!LAST)
        for (int i = tid; i < 34 * HD; i += blockDim.x) sWm[i >> 5][i & 31] = WmNext[i];
    if (tid < HD) {
        sg[tid] = g_gstate[tid];
        sWo0[tid] = Wo[tid * 2 + 0];
        sWo1[tid] = Wo[tid * 2 + 1];
    }
    __syncthreads();
    if (tid < HD) {
        float gt = bn[tid];
#pragma unroll
        for (int k = 0; k < HD; k++) gt += sg[k] * Wn[(HD + k) * HD + tid];
        gterm[tid] = gt;
    }
    __syncthreads();
    float bo0 = bo[0], bo1 = bo[1];
    int lane = tid & 31, wpb = blockDim.x >> 5;
    int gw = blockIdx.x * wpb + (tid >> 5), nw = gridDim.x * wpb;
    for (int v = gw; v < n; v += nw) {
        float h = g_h[(size_t)v * HD + lane];
        float acc = gterm[lane];
#pragma unroll
        for (int k = 0; k < HD; k++)
            acc += __shfl_sync(WARP_FULL, h, k) * sWn[k][lane];
        float hn = fmaxf(acc, 0.f);
        float p0 = hn * sWo0[lane], p1 = hn * sWo1[lane];
#pragma unroll
        for (int off = 16; off > 0; off >>= 1) {
            p0 += __shfl_xor_sync(WARP_FULL, p0, off);
            p1 += __shfl_xor_sync(WARP_FULL, p1, off);
        }
        float2 Vold = *(const float2*)&g_V[(size_t)v * 2];
        float V0 = Vold.x + p0 + bo0;
        float V1 = Vold.y + p1 + bo1;
        if (LAST) {
            if (lane == 0) {
                out[(size_t)v * 2 + 0] = V0;
                out[(size_t)v * 2 + 1] = V1;
            }
        } else {
            if (lane == 0) *(float2*)&g_V[(size_t)v * 2] = make_float2(V0, V1);
            float a = V0 * sWm[0][lane] + V1 * sWm[1][lane];
#pragma unroll
            for (int k = 0; k < HD; k++)
                a += __shfl_sync(WARP_FULL, hn, k) * sWm[2 + k][lane];
            g_A[(size_t)v * HD + lane] = a;
        }
    }
}

// ---------------------------------------------------------------- launcher
extern "C" void kernel_launch(void* const* d_in, const int* in_sizes, int n_in,
                              void* d_out, int out_size) {
    const float* PQ    = (const float*)d_in[0];
    const int*   send  = (const int*)d_in[1];
    const int*   recv  = (const int*)d_in[2];
    const float* ef    = (const float*)d_in[3];
    const float* emask = (const float*)d_in[4];
    const float* Win   = (const float*)d_in[5];
    const float* bin   = (const float*)d_in[6];
    const float* Wmsg  = (const float*)d_in[7];
    const float* bmsg  = (const float*)d_in[8];
    const float* Wg    = (const float*)d_in[9];
    const float* bg    = (const float*)d_in[10];
    const float* Wn    = (const float*)d_in[11];
    const float* bn    = (const float*)d_in[12];
    const float* Wo    = (const float*)d_in[13];
    const float* bo    = (const float*)d_in[14];
    float* out = (float*)d_out;

    int n = in_sizes[0] / 2;
    int e = in_sizes[1];

    int nch = (n + SCAN_CHUNK - 1) / SCAN_CHUNK;
    const int PB = 1184;   // persistent grid: 148 SMs * 8 blocks
    const int EB = 2048;

    k_zero<<<(n + 255) / 256, 256>>>(n);
    k_hist<<<EB, 256>>>(recv, e);
    k_chunksum<<<nch, 1024>>>(n);
    k_chunkoff<<<1, 1>>>(nch, n, e);
    k_scanfinal<<<nch, 1024>>>(n);
    k_scatter<<<EB, 256>>>(send, recv, emask, e);
    k_cfeat<<<PB, 256>>>((const float4*)ef, n);
    k_initA<<<PB, 256>>>((const float2*)PQ, Win, bin, Wmsg, n);

    float invn = 1.f / (float)n;
    for (int l = 0; l < NLAYER; l++) {
        k_agg<<<PB, 256>>>(Wmsg + (size_t)(l * 38 + 34) * HD, bmsg + l * HD, l, n);
        k_g<<<1, HD>>>(Wg + (size_t)l * 64 * HD, bg + l * HD, l, invn);
        if (l < NLAYER - 1)
            k_upd<false><<<PB, 256>>>(Wn + (size_t)l * 64 * HD, bn + l * HD,
                                      Wo + (size_t)l * HD * 2, bo + l * 2,
                                      Wmsg + (size_t)(l + 1) * 38 * HD, out, n);
        else
            k_upd<true><<<PB, 256>>>(Wn + (size_t)l * 64 * HD, bn + l * HD,
                                     Wo + (size_t)l * HD * 2, bo + l * 2,
                                     nullptr, out, n);
    }
}